// round 3
// baseline (speedup 1.0000x reference)
#include <cuda_runtime.h>
#include <math.h>

#define NB    64
#define CCH   256
#define HW    2816     // 64*44 per channel
#define GG    16
#define SHH   4
#define WW    44
#define PPX   176
#define TOPKK 22
#define TEMP_INV 8.0f
#define GATE_THR 0.05f
#define THREADS 256
#define CHUNK 32
#define NCHUNK 8
#define XR    177      // padded row stride (odd -> conflict-free)

#define TOK_ELEMS   (NB*CCH*64)          // 1,048,576
#define PRES_ELEMS  (NB*64)              // 4,096
#define MAP_ELEMS   (NB*64*44*64)        // 11,534,336

__device__ int g_cnt[NB];   // zero-init; self-resetting each launch

struct SM {
    float xsC[CHUNK*XR];    // staged channel chunk [c][p]
    float lbn4[CCH*4];      // normalized basis packed [c][k]
    float yd[4*180];        // raw projections y[k][p]
    float dotp[PPX*4];      // pooled projections [p][k]
    float sup[PPX*4];       // support [p][k]
    float pw[PPX*4];        // pool weights [p][k]
    float fe[PPX];
    float nrm[PPX];
    float tpart[8*CHUNK*4]; // token partials [warp][c][k]
    float red[32];
    float scal[16];
};

__device__ __forceinline__ float wsum(float v) {
#pragma unroll
    for (int o = 16; o; o >>= 1) v += __shfl_xor_sync(0xffffffffu, v, o);
    return v;
}
__device__ __forceinline__ float wmaxr(float v) {
#pragma unroll
    for (int o = 16; o; o >>= 1) v = fmaxf(v, __shfl_xor_sync(0xffffffffu, v, o));
    return v;
}

__device__ __forceinline__ void stage_chunk(SM& s, const float* __restrict__ xb,
                                            int chunk, int tid, int lane) {
    const float* src = xb + (size_t)chunk * CHUNK * HW;
    const int rot0 = lane + (lane >> 3);
#pragma unroll
    for (int it = 0; it < 6; ++it) {
        int idx = tid + 256 * it;            // 1408 float4 tiles (32ch x 44)
        if (idx < 1408) {
            int c = idx / 44, q = idx - 44 * c;
            float4 v = *reinterpret_cast<const float4*>(src + (size_t)c * HW + q * 4);
            float* dst = &s.xsC[c * XR + q * 4];
            float vv[4] = { v.x, v.y, v.z, v.w };
#pragma unroll
            for (int st = 0; st < 4; ++st) { int m = (rot0 + st) & 3; dst[m] = vv[m]; }
        }
    }
}

__global__ void __launch_bounds__(THREADS, 4)
fused_stripe_kernel(const float* __restrict__ x, const float* __restrict__ lb,
                    float* __restrict__ out_tok, float* __restrict__ out_pres,
                    float* __restrict__ out_smap, float* __restrict__ out_pmap)
{
    extern __shared__ float sraw[];
    SM& s = *reinterpret_cast<SM*>(sraw);
    const int tid = threadIdx.x, lane = tid & 31, wid = tid >> 5;
    const int blk = blockIdx.x;
    const int n = blk >> 4, g = blk & 15;
    const float* xb = x + (size_t)n * (CCH * HW) + (size_t)g * PPX;   // stripe is contiguous per channel

    // ---------- Phase 1: load + L2-normalize latent basis ----------
    {
        const float* lbg = lb + (size_t)g * (4 * CCH);
        float v0 = lbg[tid], v1 = lbg[CCH + tid], v2 = lbg[2 * CCH + tid], v3 = lbg[3 * CCH + tid];
        float s0 = wsum(v0 * v0), s1 = wsum(v1 * v1), s2 = wsum(v2 * v2), s3 = wsum(v3 * v3);
        if (lane == 0) { s.red[wid] = s0; s.red[8 + wid] = s1; s.red[16 + wid] = s2; s.red[24 + wid] = s3; }
        __syncthreads();
        if (tid < 4) {
            float ss = 0.f;
#pragma unroll
            for (int j = 0; j < 8; ++j) ss += s.red[tid * 8 + j];
            s.scal[tid] = 1.0f / fmaxf(sqrtf(ss), 1e-12f);
        }
        __syncthreads();
        *reinterpret_cast<float4*>(&s.lbn4[tid * 4]) =
            make_float4(v0 * s.scal[0], v1 * s.scal[1], v2 * s.scal[2], v3 * s.scal[3]);
    }

    // ---------- Phase 2: fused streaming pass (proj + fe + pooled-norm) ----------
    // 6 warps; warp jw covers 30 output pixels with 1-lane halo each side.
    float d0 = 0, d1 = 0, d2 = 0, d3 = 0, feacc = 0, nacc = 0;
    int p = 0; bool valid = false; float zl = 0, zr = 0; bool up = false, dn = false;
    if (wid < 6) {
        int p_raw = wid * 30 + lane - 1;
        p = min(max(p_raw, 0), 176);          // clamped (halo garbage discarded)
        valid = (lane >= 1) && (lane <= 30) && (p_raw >= 0) && (p_raw < PPX);
        int r = p / 44, w = p - 44 * r;
        zl = (w != 0) ? 1.f : 0.f;
        zr = (w != 43) ? 1.f : 0.f;
        up = (r > 0); dn = (r < 3);
    }

    for (int chunk = 0; chunk < NCHUNK; ++chunk) {
        __syncthreads();                       // xsC safe to overwrite
        stage_chunk(s, xb, chunk, tid, lane);
        __syncthreads();
        if (wid < 6) {
            const int cg0 = chunk * CHUNK;
#pragma unroll 4
            for (int c = 0; c < CHUNK; ++c) {
                const float* xc = &s.xsC[c * XR];
                float xm = xc[p];
                float xu = up ? xc[p - 44] : 0.f;
                float xd = dn ? xc[p + 44] : 0.f;
                float vs = xu + xm + xd;
                float vl = __shfl_up_sync(0xffffffffu, vs, 1) * zl;
                float vr = __shfl_down_sync(0xffffffffu, vs, 1) * zr;
                float pooled = vl + vs + vr;
                nacc = fmaf(pooled, pooled, nacc);
                feacc = fmaf(xm, xm, feacc);
                float4 l4 = *reinterpret_cast<const float4*>(&s.lbn4[(cg0 + c) * 4]);
                d0 = fmaf(xm, l4.x, d0); d1 = fmaf(xm, l4.y, d1);
                d2 = fmaf(xm, l4.z, d2); d3 = fmaf(xm, l4.w, d3);
            }
        }
    }
    if (valid) {
        s.yd[p] = d0; s.yd[180 + p] = d1; s.yd[360 + p] = d2; s.yd[540 + p] = d3;
        s.fe[p] = feacc * (1.0f / CCH);
        s.nrm[p] = nacc * (1.0f / 81.0f);
    }
    __syncthreads();

    // ---------- Phase 3: fe max (warp0) | pool projections (warps 1-7) ----------
    if (wid == 0) {
        float m = 0.f;
        for (int j = lane; j < PPX; j += 32) m = fmaxf(m, s.fe[j]);
        m = wmaxr(m);
        if (lane == 0) s.scal[4] = 1.0f / fmaxf(m, 1e-6f);
    } else {
        for (int idx = tid - 32; idx < PPX * 4; idx += 224) {
            int pp = idx >> 2, k = idx & 3;
            int r = pp / 44, w0 = pp - r * 44;
            const float* yk = &s.yd[k * 180];
            float acc = 0.f;
#pragma unroll
            for (int dr = -1; dr <= 1; ++dr) {
                int rr = r + dr;
                bool rok = (rr >= 0) && (rr < SHH);
#pragma unroll
                for (int dw = -1; dw <= 1; ++dw) {
                    int w2 = w0 + dw;
                    if (rok && w2 >= 0 && w2 < WW) acc += yk[rr * 44 + w2];
                }
            }
            s.dotp[idx] = acc * (1.0f / 9.0f);
        }
    }
    __syncthreads();
    const float invmax = s.scal[4];
    int pred = (tid < PPX) && (s.fe[tid] * invmax > GATE_THR);
    int cnt = __syncthreads_count(pred);

    // ---------- Phase 4: softmax routing -> support ----------
    if (tid < PPX) {
        float4 d = *reinterpret_cast<float4*>(&s.dotp[tid * 4]);
        float rn = 1.0f / fmaxf(sqrtf(s.nrm[tid]), 1e-12f);
        float sc = rn * TEMP_INV;
        float l0 = d.x * sc, l1 = d.y * sc, l2 = d.z * sc, l3 = d.w * sc;
        float m = fmaxf(fmaxf(l0, l1), fmaxf(l2, l3));
        float e0 = __expf(l0 - m), e1 = __expf(l1 - m), e2 = __expf(l2 - m), e3 = __expf(l3 - m);
        float inv = 1.0f / (e0 + e1 + e2 + e3);
        float fes = s.fe[tid] * invmax;
        float act = (cnt > 0) ? (fes > GATE_THR ? 1.f : 0.f) : (fes > 0.f ? 1.f : 0.f);
        float w_ = inv * act;
        *reinterpret_cast<float4*>(&s.sup[tid * 4]) = make_float4(e0 * w_, e1 * w_, e2 * w_, e3 * w_);
    }
    __syncthreads();

    // ---------- Phase 5 (overlapped): pool sums | top-22 presence | smap part A ----------
    if (wid == 0) {
        float s0 = 0, s1 = 0, s2 = 0, s3 = 0;
        for (int pp = lane; pp < PPX; pp += 32) {
            float4 v = *reinterpret_cast<float4*>(&s.sup[pp * 4]);
            s0 += v.x; s1 += v.y; s2 += v.z; s3 += v.w;
        }
        s0 = wsum(s0); s1 = wsum(s1); s2 = wsum(s2); s3 = wsum(s3);
        if (lane == 0) {
            s.scal[8]  = 1.0f / fmaxf(s0, 1e-6f);
            s.scal[9]  = 1.0f / fmaxf(s1, 1e-6f);
            s.scal[10] = 1.0f / fmaxf(s2, 1e-6f);
            s.scal[11] = 1.0f / fmaxf(s3, 1e-6f);
        }
    } else if (wid >= 4) {
        const int k = wid - 4;
        float v[6];
#pragma unroll
        for (int j = 0; j < 6; ++j) {
            int pp = lane + 32 * j;
            v[j] = (pp < PPX) ? s.sup[pp * 4 + k] : -1.0f;
        }
        float sum = 0.f;
        for (int it = 0; it < TOPKK; ++it) {
            float lm = v[0]; int li = 0;
#pragma unroll
            for (int j = 1; j < 6; ++j) { if (v[j] > lm) { lm = v[j]; li = j; } }
            float wm = wmaxr(lm);
            unsigned msk = __ballot_sync(0xffffffffu, lm == wm);
            int src = __ffs(msk) - 1;
            if (lane == src) v[li] = -1.0f;
            sum += wm;
        }
        if (lane == 0) {
            out_pres[n * 64 + g * 4 + k] = sum * (1.0f / TOPKK);   // raw; normalized by last CTA
            __threadfence();
        }
    } else {
        // warps 1-3: smap scatter, first half (float4 slots 0..1407)
        float* smb = out_smap + (size_t)n * (HW * 64) + (size_t)g * (PPX * 64);
        const float4 z4 = make_float4(0.f, 0.f, 0.f, 0.f);
        for (int idx = (wid - 1) * 32 + lane; idx < 1408; idx += 96) {
            int pp = idx >> 4, qd = idx & 15;
            float4 sv = (qd == g) ? *reinterpret_cast<float4*>(&s.sup[pp * 4]) : z4;
            *reinterpret_cast<float4*>(smb + (size_t)idx * 4) = sv;
        }
    }
    __syncthreads();

    // ---------- Phase 6: pool weights ----------
    if (tid < PPX) {
        float4 v = *reinterpret_cast<float4*>(&s.sup[tid * 4]);
        *reinterpret_cast<float4*>(&s.pw[tid * 4]) =
            make_float4(v.x * s.scal[8], v.y * s.scal[9], v.z * s.scal[10], v.w * s.scal[11]);
    }
    __syncthreads();

    // ---------- Phase 7: tokens via second chunk stream ----------
    for (int chunk = 0; chunk < NCHUNK; ++chunk) {
        stage_chunk(s, xb, chunk, tid, lane);
        __syncthreads();
        const int p0 = wid * 22;
        float t0 = 0, t1 = 0, t2 = 0, t3 = 0;
        const float* xc = &s.xsC[lane * XR];
#pragma unroll 2
        for (int i = 0; i < 22; ++i) {
            float4 w4 = *reinterpret_cast<const float4*>(&s.pw[(p0 + i) * 4]);
            float xv = xc[p0 + i];
            t0 = fmaf(xv, w4.x, t0); t1 = fmaf(xv, w4.y, t1);
            t2 = fmaf(xv, w4.z, t2); t3 = fmaf(xv, w4.w, t3);
        }
        *reinterpret_cast<float4*>(&s.tpart[(wid * 32 + lane) * 4]) = make_float4(t0, t1, t2, t3);
        __syncthreads();
        if (wid == 0) {
            float4 acc = *reinterpret_cast<float4*>(&s.tpart[lane * 4]);
#pragma unroll
            for (int j = 1; j < 8; ++j) {
                float4 v = *reinterpret_cast<float4*>(&s.tpart[(j * 32 + lane) * 4]);
                acc.x += v.x; acc.y += v.y; acc.z += v.z; acc.w += v.w;
            }
            int c = chunk * 32 + lane;
            *reinterpret_cast<float4*>(out_tok + ((size_t)(n * CCH + c) * 64 + g * 4)) = acc;
        }
    }

    // ---------- Phase 8: smap part B + pmap scatter ----------
    {
        float* smb = out_smap + (size_t)n * (HW * 64) + (size_t)g * (PPX * 64);
        float* pmb = out_pmap + (size_t)n * (HW * 64) + (size_t)g * (PPX * 64);
        const float4 z4 = make_float4(0.f, 0.f, 0.f, 0.f);
        for (int idx = 1408 + tid; idx < 2816; idx += 256) {
            int pp = idx >> 4, qd = idx & 15;
            float4 sv = (qd == g) ? *reinterpret_cast<float4*>(&s.sup[pp * 4]) : z4;
            *reinterpret_cast<float4*>(smb + (size_t)idx * 4) = sv;
        }
#pragma unroll
        for (int i = 0; i < 11; ++i) {
            int idx = tid + 256 * i;
            int pp = idx >> 4, qd = idx & 15;
            float4 pv = (qd == g) ? *reinterpret_cast<float4*>(&s.pw[pp * 4]) : z4;
            *reinterpret_cast<float4*>(pmb + (size_t)idx * 4) = pv;
        }
    }

    // ---------- Phase 9: last CTA of batch n normalizes presence ----------
    __syncthreads();
    if (tid == 0) {
        __threadfence();
        int old = atomicAdd(&g_cnt[n], 1);
        s.red[0] = (old == 15) ? 1.f : 0.f;
    }
    __syncthreads();
    if (s.red[0] != 0.f && wid == 0) {
        __threadfence();
        float a = out_pres[n * 64 + lane];
        float b = out_pres[n * 64 + 32 + lane];
        float t = wsum(a + b);
        float inv = 1.0f / fmaxf(t, 1e-6f);
        out_pres[n * 64 + lane] = a * inv;
        out_pres[n * 64 + 32 + lane] = b * inv;
        if (lane == 0) g_cnt[n] = 0;   // self-reset for next launch/replay
    }
}

extern "C" void kernel_launch(void* const* d_in, const int* in_sizes, int n_in,
                              void* d_out, int out_size)
{
    const float* x  = (const float*)d_in[0];
    const float* lb = (const float*)d_in[1];
    float* out = (float*)d_out;

    float* tok  = out;
    float* pres = out + TOK_ELEMS;
    float* smap = out + TOK_ELEMS + PRES_ELEMS;
    float* pmap = out + TOK_ELEMS + PRES_ELEMS + MAP_ELEMS;

    cudaFuncSetAttribute(fused_stripe_kernel,
                         cudaFuncAttributeMaxDynamicSharedMemorySize, (int)sizeof(SM));
    fused_stripe_kernel<<<NB * GG, THREADS, sizeof(SM)>>>(x, lb, tok, pres, smap, pmap);
}

// round 4
// speedup vs baseline: 1.0352x; 1.0352x over previous
#include <cuda_runtime.h>
#include <math.h>

#define NB    64
#define CCH   256
#define HW    2816     // 64*44 per channel
#define GG    16
#define WW    44
#define PPX   176
#define TOPKK 22
#define TEMP_INV 8.0f
#define GATE_THR 0.05f
#define THREADS 256

#define TOK_ELEMS   (NB*CCH*64)
#define PRES_ELEMS  (NB*64)
#define MAP_ELEMS   (NB*64*44*64)

__device__ int g_cnt[NB];   // zero-init; self-resetting each launch

struct __align__(16) SM {
    float lbn4[CCH*4];      // normalized basis packed [c][k]   (offset 0, 16B aligned)
    float dotp[PPX*4];      // pooled projections [p][k]
    float sup[PPX*4];       // support [p][k]
    float pw[PPX*4];        // pool weights [p][k]
    float fe[PPX];
    float nrm[PPX];
    float red[32];
    float scal[16];
};

__device__ __forceinline__ float wsum(float v) {
#pragma unroll
    for (int o = 16; o; o >>= 1) v += __shfl_xor_sync(0xffffffffu, v, o);
    return v;
}
__device__ __forceinline__ float wmaxr(float v) {
#pragma unroll
    for (int o = 16; o; o >>= 1) v = fmaxf(v, __shfl_xor_sync(0xffffffffu, v, o));
    return v;
}

__global__ void __launch_bounds__(THREADS, 6)
fused_stripe_kernel(const float* __restrict__ x, const float* __restrict__ lb,
                    float* __restrict__ out_tok, float* __restrict__ out_pres,
                    float* __restrict__ out_smap, float* __restrict__ out_pmap)
{
    __shared__ SM s;
    const int tid = threadIdx.x, lane = tid & 31, wid = tid >> 5;
    const int blk = blockIdx.x;
    const int n = blk >> 4, g = blk & 15;
    const float* xb = x + (size_t)n * (CCH * HW) + (size_t)g * PPX;  // stripe contiguous per channel

    // ---------- Phase 1: load + L2-normalize latent basis ----------
    {
        const float* lbg = lb + (size_t)g * (4 * CCH);
        float v0 = lbg[tid], v1 = lbg[CCH + tid], v2 = lbg[2 * CCH + tid], v3 = lbg[3 * CCH + tid];
        float s0 = wsum(v0 * v0), s1 = wsum(v1 * v1), s2 = wsum(v2 * v2), s3 = wsum(v3 * v3);
        if (lane == 0) { s.red[wid] = s0; s.red[8 + wid] = s1; s.red[16 + wid] = s2; s.red[24 + wid] = s3; }
        __syncthreads();
        if (tid < 4) {
            float ss = 0.f;
#pragma unroll
            for (int j = 0; j < 8; ++j) ss += s.red[tid * 8 + j];
            s.scal[tid] = 1.0f / fmaxf(sqrtf(ss), 1e-12f);
        }
        __syncthreads();
        *reinterpret_cast<float4*>(&s.lbn4[tid * 4]) =
            make_float4(v0 * s.scal[0], v1 * s.scal[1], v2 * s.scal[2], v3 * s.scal[3]);
        __syncthreads();
    }

    // ---------- Phase 2: streaming stencil pass straight from GMEM ----------
    // warp jw: loads 8 columns [jw*6-1 .. jw*6+6] x 4 rows; outputs 6 interior cols.
    // Vertical 3-tap via shfl +/-8, horizontal via shfl +/-1. Zero pad = halo loads 0.
    {
        const unsigned FULL = 0xffffffffu;
        const int jw = wid, wc = lane & 7, r = lane >> 3;
        const int wl = jw * 6 + wc - 1;                 // loaded column
        const bool inb = (wl >= 0) && (wl < WW);
        const int wout = jw * 6 + wc - 1;               // output column (lanes wc=1..6)
        const bool valid = (wc >= 1) && (wc <= 6) && (wout < WW);
        const int p = r * WW + (inb ? wl : 0);
        const float fu = (r > 0) ? 1.f : 0.f, fd = (r < 3) ? 1.f : 0.f;
        const float* xp = xb + p;

        float pd0 = 0, pd1 = 0, pd2 = 0, pd3 = 0, feacc = 0, nacc = 0;
        const float4* lbv = reinterpret_cast<const float4*>(s.lbn4);
#pragma unroll 4
        for (int c = 0; c < CCH; ++c) {
            float xm = inb ? __ldg(xp) : 0.f;
            xp += HW;
            float xu = __shfl_up_sync(FULL, xm, 8) * fu;
            float xd = __shfl_down_sync(FULL, xm, 8) * fd;
            float vs = xu + xm + xd;
            float vl = __shfl_up_sync(FULL, vs, 1);
            float vr = __shfl_down_sync(FULL, vs, 1);
            float pooled = vl + vs + vr;                 // halo lanes hold 0 at edges
            float4 l4 = lbv[c];
            pd0 = fmaf(pooled, l4.x, pd0); pd1 = fmaf(pooled, l4.y, pd1);
            pd2 = fmaf(pooled, l4.z, pd2); pd3 = fmaf(pooled, l4.w, pd3);
            feacc = fmaf(xm, xm, feacc);
            nacc  = fmaf(pooled, pooled, nacc);
        }
        if (valid) {
            const int po = r * WW + wout;
            *reinterpret_cast<float4*>(&s.dotp[po * 4]) =
                make_float4(pd0 * (1.f/9.f), pd1 * (1.f/9.f), pd2 * (1.f/9.f), pd3 * (1.f/9.f));
            s.fe[po]  = feacc * (1.0f / CCH);
            s.nrm[po] = nacc * (1.0f / 81.0f);
        }
    }
    __syncthreads();

    // ---------- Phase 3: fe max ----------
    if (wid == 0) {
        float m = 0.f;
        for (int j = lane; j < PPX; j += 32) m = fmaxf(m, s.fe[j]);
        m = wmaxr(m);
        if (lane == 0) s.scal[4] = 1.0f / fmaxf(m, 1e-6f);
    }
    __syncthreads();
    const float invmax = s.scal[4];
    int pred = (tid < PPX) && (s.fe[tid] * invmax > GATE_THR);
    int cnt = __syncthreads_count(pred);

    // ---------- Phase 4: softmax routing -> support ----------
    if (tid < PPX) {
        float4 d = *reinterpret_cast<float4*>(&s.dotp[tid * 4]);
        float rn = 1.0f / fmaxf(sqrtf(s.nrm[tid]), 1e-12f);
        float sc = rn * TEMP_INV;
        float l0 = d.x * sc, l1 = d.y * sc, l2 = d.z * sc, l3 = d.w * sc;
        float m = fmaxf(fmaxf(l0, l1), fmaxf(l2, l3));
        float e0 = __expf(l0 - m), e1 = __expf(l1 - m), e2 = __expf(l2 - m), e3 = __expf(l3 - m);
        float inv = 1.0f / (e0 + e1 + e2 + e3);
        float fes = s.fe[tid] * invmax;
        float act = (cnt > 0) ? (fes > GATE_THR ? 1.f : 0.f) : (fes > 0.f ? 1.f : 0.f);
        float w_ = inv * act;
        *reinterpret_cast<float4*>(&s.sup[tid * 4]) = make_float4(e0 * w_, e1 * w_, e2 * w_, e3 * w_);
    }
    __syncthreads();

    // ---------- Phase 5 (overlapped): pool sums | top-22 presence | smap part A ----------
    if (wid == 0) {
        float s0 = 0, s1 = 0, s2 = 0, s3 = 0;
        for (int pp = lane; pp < PPX; pp += 32) {
            float4 v = *reinterpret_cast<float4*>(&s.sup[pp * 4]);
            s0 += v.x; s1 += v.y; s2 += v.z; s3 += v.w;
        }
        s0 = wsum(s0); s1 = wsum(s1); s2 = wsum(s2); s3 = wsum(s3);
        if (lane == 0) {
            s.scal[8]  = 1.0f / fmaxf(s0, 1e-6f);
            s.scal[9]  = 1.0f / fmaxf(s1, 1e-6f);
            s.scal[10] = 1.0f / fmaxf(s2, 1e-6f);
            s.scal[11] = 1.0f / fmaxf(s3, 1e-6f);
        }
    } else if (wid >= 4) {
        const int k = wid - 4;
        float v[6];
#pragma unroll
        for (int j = 0; j < 6; ++j) {
            int pp = lane + 32 * j;
            v[j] = (pp < PPX) ? s.sup[pp * 4 + k] : -1.0f;
        }
        float sum = 0.f;
        for (int it = 0; it < TOPKK; ++it) {
            float lm = v[0]; int li = 0;
#pragma unroll
            for (int j = 1; j < 6; ++j) { if (v[j] > lm) { lm = v[j]; li = j; } }
            float wm = wmaxr(lm);
            unsigned msk = __ballot_sync(0xffffffffu, lm == wm);
            int src = __ffs(msk) - 1;
            if (lane == src) v[li] = -1.0f;
            sum += wm;
        }
        if (lane == 0) {
            out_pres[n * 64 + g * 4 + k] = sum * (1.0f / TOPKK);   // raw; normalized by last CTA
            __threadfence();
        }
    } else {
        // warps 1-3: smap scatter, first half (float4 slots 0..1407)
        float* smb = out_smap + (size_t)n * (HW * 64) + (size_t)g * (PPX * 64);
        const float4 z4 = make_float4(0.f, 0.f, 0.f, 0.f);
        for (int idx = (wid - 1) * 32 + lane; idx < 1408; idx += 96) {
            int pp = idx >> 4, qd = idx & 15;
            float4 sv = (qd == g) ? *reinterpret_cast<float4*>(&s.sup[pp * 4]) : z4;
            *reinterpret_cast<float4*>(smb + (size_t)idx * 4) = sv;
        }
    }
    __syncthreads();

    // ---------- Phase 6: pool weights ----------
    if (tid < PPX) {
        float4 v = *reinterpret_cast<float4*>(&s.sup[tid * 4]);
        *reinterpret_cast<float4*>(&s.pw[tid * 4]) =
            make_float4(v.x * s.scal[8], v.y * s.scal[9], v.z * s.scal[10], v.w * s.scal[11]);
    }
    __syncthreads();

    // ---------- Phase 7: tokens, thread = channel, vectorized GMEM re-read ----------
    {
        const int c = tid;
        const float4* xp4 = reinterpret_cast<const float4*>(xb + (size_t)c * HW);
        const float4* pwv = reinterpret_cast<const float4*>(s.pw);
        float t0 = 0, t1 = 0, t2 = 0, t3 = 0;
#pragma unroll 4
        for (int i = 0; i < 44; ++i) {
            float4 xv = __ldg(&xp4[i]);
            float4 w0 = pwv[4 * i + 0], w1 = pwv[4 * i + 1], w2 = pwv[4 * i + 2], w3 = pwv[4 * i + 3];
            t0 = fmaf(xv.x, w0.x, t0); t1 = fmaf(xv.x, w0.y, t1); t2 = fmaf(xv.x, w0.z, t2); t3 = fmaf(xv.x, w0.w, t3);
            t0 = fmaf(xv.y, w1.x, t0); t1 = fmaf(xv.y, w1.y, t1); t2 = fmaf(xv.y, w1.z, t2); t3 = fmaf(xv.y, w1.w, t3);
            t0 = fmaf(xv.z, w2.x, t0); t1 = fmaf(xv.z, w2.y, t1); t2 = fmaf(xv.z, w2.z, t2); t3 = fmaf(xv.z, w2.w, t3);
            t0 = fmaf(xv.w, w3.x, t0); t1 = fmaf(xv.w, w3.y, t1); t2 = fmaf(xv.w, w3.z, t2); t3 = fmaf(xv.w, w3.w, t3);
        }
        *reinterpret_cast<float4*>(out_tok + ((size_t)(n * CCH + c) * 64 + g * 4)) =
            make_float4(t0, t1, t2, t3);
    }

    // ---------- Phase 8: smap part B + pmap scatter ----------
    {
        float* smb = out_smap + (size_t)n * (HW * 64) + (size_t)g * (PPX * 64);
        float* pmb = out_pmap + (size_t)n * (HW * 64) + (size_t)g * (PPX * 64);
        const float4 z4 = make_float4(0.f, 0.f, 0.f, 0.f);
        for (int idx = 1408 + tid; idx < 2816; idx += 256) {
            int pp = idx >> 4, qd = idx & 15;
            float4 sv = (qd == g) ? *reinterpret_cast<float4*>(&s.sup[pp * 4]) : z4;
            *reinterpret_cast<float4*>(smb + (size_t)idx * 4) = sv;
        }
#pragma unroll
        for (int i = 0; i < 11; ++i) {
            int idx = tid + 256 * i;
            int pp = idx >> 4, qd = idx & 15;
            float4 pv = (qd == g) ? *reinterpret_cast<float4*>(&s.pw[pp * 4]) : z4;
            *reinterpret_cast<float4*>(pmb + (size_t)idx * 4) = pv;
        }
    }

    // ---------- Phase 9: last CTA of batch n normalizes presence ----------
    __syncthreads();
    if (tid == 0) {
        __threadfence();
        int old = atomicAdd(&g_cnt[n], 1);
        s.red[0] = (old == 15) ? 1.f : 0.f;
    }
    __syncthreads();
    if (s.red[0] != 0.f && wid == 0) {
        __threadfence();
        float a = out_pres[n * 64 + lane];
        float b = out_pres[n * 64 + 32 + lane];
        float t = wsum(a + b);
        float inv = 1.0f / fmaxf(t, 1e-6f);
        out_pres[n * 64 + lane] = a * inv;
        out_pres[n * 64 + 32 + lane] = b * inv;
        if (lane == 0) g_cnt[n] = 0;   // self-reset for next launch/replay
    }
}

extern "C" void kernel_launch(void* const* d_in, const int* in_sizes, int n_in,
                              void* d_out, int out_size)
{
    const float* x  = (const float*)d_in[0];
    const float* lb = (const float*)d_in[1];
    float* out = (float*)d_out;

    float* tok  = out;
    float* pres = out + TOK_ELEMS;
    float* smap = out + TOK_ELEMS + PRES_ELEMS;
    float* pmap = out + TOK_ELEMS + PRES_ELEMS + MAP_ELEMS;

    fused_stripe_kernel<<<NB * GG, THREADS>>>(x, lb, tok, pres, smap, pmap);
}

// round 5
// speedup vs baseline: 1.0370x; 1.0018x over previous
#include <cuda_runtime.h>
#include <math.h>

#define NB    64
#define CCH   256
#define HW    2816     // 64*44 per channel
#define WW    44
#define PPX   176
#define TOPKK 22
#define TEMP_INV 8.0f
#define GATE_THR 0.05f
#define THREADS 256

#define TOK_ELEMS   (NB*CCH*64)
#define PRES_ELEMS  (NB*64)
#define MAP_ELEMS   (NB*64*44*64)

__device__ int g_cnt[NB];   // zero-init; self-resetting each launch

struct __align__(16) SM {
    float lbn4[CCH*4];      // normalized basis packed [c][k]
    float pdP[4*PPX*4];     // dotp partials per channel-subset [cs][p][k]
    float feP[4*PPX];       // fe partials
    float nrmP[4*PPX];      // nrm partials
    float dotp[PPX*4];
    float sup[PPX*4];
    float pw[PPX*4];
    float pwT[4*PPX];       // transposed pool weights [k][p]
    float fe[PPX];
    float nrm[PPX];
    float red[32];
    float scal[16];
};

__device__ __forceinline__ float wsum(float v) {
#pragma unroll
    for (int o = 16; o; o >>= 1) v += __shfl_xor_sync(0xffffffffu, v, o);
    return v;
}
__device__ __forceinline__ float wmaxr(float v) {
#pragma unroll
    for (int o = 16; o; o >>= 1) v = fmaxf(v, __shfl_xor_sync(0xffffffffu, v, o));
    return v;
}

__global__ void __launch_bounds__(THREADS, 4)
fused_stripe_kernel(const float* __restrict__ x, const float* __restrict__ lb,
                    float* __restrict__ out_tok, float* __restrict__ out_pres,
                    float* __restrict__ out_smap, float* __restrict__ out_pmap)
{
    __shared__ SM s;
    const unsigned FULL = 0xffffffffu;
    const int tid = threadIdx.x, lane = tid & 31, wid = tid >> 5;
    const int blk = blockIdx.x;
    const int n = blk >> 4, g = blk & 15;
    const float* xb = x + (size_t)n * (CCH * HW) + (size_t)g * PPX;

    // ---------- Phase 1: load + L2-normalize latent basis ----------
    {
        const float* lbg = lb + (size_t)g * (4 * CCH);
        float v0 = lbg[tid], v1 = lbg[CCH + tid], v2 = lbg[2 * CCH + tid], v3 = lbg[3 * CCH + tid];
        float s0 = wsum(v0 * v0), s1 = wsum(v1 * v1), s2 = wsum(v2 * v2), s3 = wsum(v3 * v3);
        if (lane == 0) { s.red[wid] = s0; s.red[8 + wid] = s1; s.red[16 + wid] = s2; s.red[24 + wid] = s3; }
        __syncthreads();
        if (tid < 4) {
            float ss = 0.f;
#pragma unroll
            for (int j = 0; j < 8; ++j) ss += s.red[tid * 8 + j];
            s.scal[tid] = 1.0f / fmaxf(sqrtf(ss), 1e-12f);
        }
        __syncthreads();
        *reinterpret_cast<float4*>(&s.lbn4[tid * 4]) =
            make_float4(v0 * s.scal[0], v1 * s.scal[1], v2 * s.scal[2], v3 * s.scal[3]);
        __syncthreads();
    }

    // ---------- Phase 2: float4 stencil pass straight from GMEM ----------
    // warp: rp = row-pair (0/1), cs = channel subset (c % 4).
    // lanes 0..21: lr = lane/11 (row within pair), q = lane%11 (float4 col block).
    {
        const int rp = wid >> 2, cs = wid & 3;
        const bool act2 = (lane < 22);
        const int lr = (lane < 22) ? (lane / 11) : 0;
        const int q  = (lane < 22) ? (lane - 11 * lr) : 0;
        const int r  = rp * 2 + lr;
        const int po = act2 ? (r * WW + q * 4) : 0;
        const bool ha = act2 && (r > 0), hc = act2 && (r < 3);
        const float fq0 = (q > 0) ? 1.f : 0.f, fq10 = (q < 10) ? 1.f : 0.f;
        const float4 z4 = make_float4(0.f, 0.f, 0.f, 0.f);

        float4 pd0 = z4, pd1 = z4, pd2 = z4, pd3 = z4, fe4 = z4, nr4 = z4;
        const float4* lbv = reinterpret_cast<const float4*>(s.lbn4);
        const float* pc = xb + po + (size_t)cs * HW;
#pragma unroll 2
        for (int c = cs; c < CCH; c += 4) {
            float4 xm = act2 ? *reinterpret_cast<const float4*>(pc) : z4;
            float4 xu = ha ? *reinterpret_cast<const float4*>(pc - WW) : z4;
            float4 xd = hc ? *reinterpret_cast<const float4*>(pc + WW) : z4;
            pc += 4 * HW;
            float4 vs = make_float4(xu.x + xm.x + xd.x, xu.y + xm.y + xd.y,
                                    xu.z + xm.z + xd.z, xu.w + xm.w + xd.w);
            float lw = __shfl_up_sync(FULL, vs.w, 1) * fq0;
            float rw = __shfl_down_sync(FULL, vs.x, 1) * fq10;
            float4 pl;
            pl.x = lw + vs.x + vs.y;
            pl.y = vs.x + vs.y + vs.z;
            pl.z = vs.y + vs.z + vs.w;
            pl.w = vs.z + vs.w + rw;
            float4 l4 = lbv[c];
            pd0.x = fmaf(pl.x, l4.x, pd0.x); pd0.y = fmaf(pl.y, l4.x, pd0.y);
            pd0.z = fmaf(pl.z, l4.x, pd0.z); pd0.w = fmaf(pl.w, l4.x, pd0.w);
            pd1.x = fmaf(pl.x, l4.y, pd1.x); pd1.y = fmaf(pl.y, l4.y, pd1.y);
            pd1.z = fmaf(pl.z, l4.y, pd1.z); pd1.w = fmaf(pl.w, l4.y, pd1.w);
            pd2.x = fmaf(pl.x, l4.z, pd2.x); pd2.y = fmaf(pl.y, l4.z, pd2.y);
            pd2.z = fmaf(pl.z, l4.z, pd2.z); pd2.w = fmaf(pl.w, l4.z, pd2.w);
            pd3.x = fmaf(pl.x, l4.w, pd3.x); pd3.y = fmaf(pl.y, l4.w, pd3.y);
            pd3.z = fmaf(pl.z, l4.w, pd3.z); pd3.w = fmaf(pl.w, l4.w, pd3.w);
            fe4.x = fmaf(xm.x, xm.x, fe4.x); fe4.y = fmaf(xm.y, xm.y, fe4.y);
            fe4.z = fmaf(xm.z, xm.z, fe4.z); fe4.w = fmaf(xm.w, xm.w, fe4.w);
            nr4.x = fmaf(pl.x, pl.x, nr4.x); nr4.y = fmaf(pl.y, pl.y, nr4.y);
            nr4.z = fmaf(pl.z, pl.z, nr4.z); nr4.w = fmaf(pl.w, pl.w, nr4.w);
        }
        if (act2) {
            float* pb = &s.pdP[(cs * PPX + po) * 4];
            *reinterpret_cast<float4*>(pb + 0)  = make_float4(pd0.x, pd1.x, pd2.x, pd3.x);
            *reinterpret_cast<float4*>(pb + 4)  = make_float4(pd0.y, pd1.y, pd2.y, pd3.y);
            *reinterpret_cast<float4*>(pb + 8)  = make_float4(pd0.z, pd1.z, pd2.z, pd3.z);
            *reinterpret_cast<float4*>(pb + 12) = make_float4(pd0.w, pd1.w, pd2.w, pd3.w);
            *reinterpret_cast<float4*>(&s.feP[cs * PPX + po])  = fe4;
            *reinterpret_cast<float4*>(&s.nrmP[cs * PPX + po]) = nr4;
        }
    }
    __syncthreads();

    // ---------- Phase 2b: combine channel-subset partials ----------
    if (tid < PPX) {
        float4 d = make_float4(0.f, 0.f, 0.f, 0.f);
        float fe = 0.f, nm = 0.f;
#pragma unroll
        for (int cs = 0; cs < 4; ++cs) {
            float4 v = *reinterpret_cast<float4*>(&s.pdP[(cs * PPX + tid) * 4]);
            d.x += v.x; d.y += v.y; d.z += v.z; d.w += v.w;
            fe += s.feP[cs * PPX + tid];
            nm += s.nrmP[cs * PPX + tid];
        }
        *reinterpret_cast<float4*>(&s.dotp[tid * 4]) =
            make_float4(d.x * (1.f/9.f), d.y * (1.f/9.f), d.z * (1.f/9.f), d.w * (1.f/9.f));
        s.fe[tid]  = fe * (1.0f / CCH);
        s.nrm[tid] = nm * (1.0f / 81.0f);
    }
    __syncthreads();

    // ---------- Phase 3: fe max ----------
    if (wid == 0) {
        float m = 0.f;
        for (int j = lane; j < PPX; j += 32) m = fmaxf(m, s.fe[j]);
        m = wmaxr(m);
        if (lane == 0) s.scal[4] = 1.0f / fmaxf(m, 1e-6f);
    }
    __syncthreads();
    const float invmax = s.scal[4];
    int pred = (tid < PPX) && (s.fe[tid] * invmax > GATE_THR);
    int cnt = __syncthreads_count(pred);

    // ---------- Phase 4: softmax routing -> support ----------
    if (tid < PPX) {
        float4 d = *reinterpret_cast<float4*>(&s.dotp[tid * 4]);
        float rn = 1.0f / fmaxf(sqrtf(s.nrm[tid]), 1e-12f);
        float sc = rn * TEMP_INV;
        float l0 = d.x * sc, l1 = d.y * sc, l2 = d.z * sc, l3 = d.w * sc;
        float m = fmaxf(fmaxf(l0, l1), fmaxf(l2, l3));
        float e0 = __expf(l0 - m), e1 = __expf(l1 - m), e2 = __expf(l2 - m), e3 = __expf(l3 - m);
        float inv = 1.0f / (e0 + e1 + e2 + e3);
        float fes = s.fe[tid] * invmax;
        float act = (cnt > 0) ? (fes > GATE_THR ? 1.f : 0.f) : (fes > 0.f ? 1.f : 0.f);
        float w_ = inv * act;
        *reinterpret_cast<float4*>(&s.sup[tid * 4]) = make_float4(e0 * w_, e1 * w_, e2 * w_, e3 * w_);
    }
    __syncthreads();

    // ---------- Phase 5 (overlapped): pool sums | top-22 presence | smap part A ----------
    if (wid == 0) {
        float s0 = 0, s1 = 0, s2 = 0, s3 = 0;
        for (int pp = lane; pp < PPX; pp += 32) {
            float4 v = *reinterpret_cast<float4*>(&s.sup[pp * 4]);
            s0 += v.x; s1 += v.y; s2 += v.z; s3 += v.w;
        }
        s0 = wsum(s0); s1 = wsum(s1); s2 = wsum(s2); s3 = wsum(s3);
        if (lane == 0) {
            s.scal[8]  = 1.0f / fmaxf(s0, 1e-6f);
            s.scal[9]  = 1.0f / fmaxf(s1, 1e-6f);
            s.scal[10] = 1.0f / fmaxf(s2, 1e-6f);
            s.scal[11] = 1.0f / fmaxf(s3, 1e-6f);
        }
    } else if (wid >= 4) {
        const int k = wid - 4;
        float v[6];
#pragma unroll
        for (int j = 0; j < 6; ++j) {
            int pp = lane + 32 * j;
            v[j] = (pp < PPX) ? s.sup[pp * 4 + k] : -1.0f;
        }
        float sum = 0.f;
        for (int it = 0; it < TOPKK; ++it) {
            float lm = v[0]; int li = 0;
#pragma unroll
            for (int j = 1; j < 6; ++j) { if (v[j] > lm) { lm = v[j]; li = j; } }
            float wm = wmaxr(lm);
            unsigned msk = __ballot_sync(0xffffffffu, lm == wm);
            int src = __ffs(msk) - 1;
            if (lane == src) v[li] = -1.0f;
            sum += wm;
        }
        if (lane == 0) {
            out_pres[n * 64 + g * 4 + k] = sum * (1.0f / TOPKK);
            __threadfence();
        }
    } else {
        // warps 1-3: smap scatter, first half (float4 slots 0..1407)
        float* smb = out_smap + (size_t)n * (HW * 64) + (size_t)g * (PPX * 64);
        const float4 z4 = make_float4(0.f, 0.f, 0.f, 0.f);
        for (int idx = (wid - 1) * 32 + lane; idx < 1408; idx += 96) {
            int pp = idx >> 4, qd = idx & 15;
            float4 sv = (qd == g) ? *reinterpret_cast<float4*>(&s.sup[pp * 4]) : z4;
            *reinterpret_cast<float4*>(smb + (size_t)idx * 4) = sv;
        }
    }
    __syncthreads();

    // ---------- Phase 6: pool weights (both layouts) ----------
    if (tid < PPX) {
        float4 v = *reinterpret_cast<float4*>(&s.sup[tid * 4]);
        float4 w = make_float4(v.x * s.scal[8], v.y * s.scal[9], v.z * s.scal[10], v.w * s.scal[11]);
        *reinterpret_cast<float4*>(&s.pw[tid * 4]) = w;
        s.pwT[0 * PPX + tid] = w.x;
        s.pwT[1 * PPX + tid] = w.y;
        s.pwT[2 * PPX + tid] = w.z;
        s.pwT[3 * PPX + tid] = w.w;
    }
    __syncthreads();

    // ---------- Phase 7: tokens — 8-lane channel groups, coalesced float4 reads ----------
    {
        const int grp = lane >> 3, gl = lane & 7;
        const int cbase = wid * 32;
#pragma unroll 2
        for (int pass = 0; pass < 8; ++pass) {
            const int c = cbase + pass * 4 + grp;
            const float* xc = xb + (size_t)c * HW;
            float a0 = 0, a1 = 0, a2 = 0, a3 = 0;
#pragma unroll
            for (int it = 0; it < 6; ++it) {
                int p0 = it * 32 + gl * 4;
                if (p0 < PPX) {
                    float4 xv = *reinterpret_cast<const float4*>(xc + p0);
                    float4 w0 = *reinterpret_cast<const float4*>(&s.pwT[0 * PPX + p0]);
                    float4 w1 = *reinterpret_cast<const float4*>(&s.pwT[1 * PPX + p0]);
                    float4 w2 = *reinterpret_cast<const float4*>(&s.pwT[2 * PPX + p0]);
                    float4 w3 = *reinterpret_cast<const float4*>(&s.pwT[3 * PPX + p0]);
                    a0 = fmaf(xv.x, w0.x, fmaf(xv.y, w0.y, fmaf(xv.z, w0.z, fmaf(xv.w, w0.w, a0))));
                    a1 = fmaf(xv.x, w1.x, fmaf(xv.y, w1.y, fmaf(xv.z, w1.z, fmaf(xv.w, w1.w, a1))));
                    a2 = fmaf(xv.x, w2.x, fmaf(xv.y, w2.y, fmaf(xv.z, w2.z, fmaf(xv.w, w2.w, a2))));
                    a3 = fmaf(xv.x, w3.x, fmaf(xv.y, w3.y, fmaf(xv.z, w3.z, fmaf(xv.w, w3.w, a3))));
                }
            }
#pragma unroll
            for (int m = 1; m <= 4; m <<= 1) {
                a0 += __shfl_xor_sync(FULL, a0, m);
                a1 += __shfl_xor_sync(FULL, a1, m);
                a2 += __shfl_xor_sync(FULL, a2, m);
                a3 += __shfl_xor_sync(FULL, a3, m);
            }
            if (gl == 0)
                *reinterpret_cast<float4*>(out_tok + ((size_t)(n * CCH + c) * 64 + g * 4)) =
                    make_float4(a0, a1, a2, a3);
        }
    }

    // ---------- Phase 8: smap part B + pmap scatter ----------
    {
        float* smb = out_smap + (size_t)n * (HW * 64) + (size_t)g * (PPX * 64);
        float* pmb = out_pmap + (size_t)n * (HW * 64) + (size_t)g * (PPX * 64);
        const float4 z4 = make_float4(0.f, 0.f, 0.f, 0.f);
        for (int idx = 1408 + tid; idx < 2816; idx += 256) {
            int pp = idx >> 4, qd = idx & 15;
            float4 sv = (qd == g) ? *reinterpret_cast<float4*>(&s.sup[pp * 4]) : z4;
            *reinterpret_cast<float4*>(smb + (size_t)idx * 4) = sv;
        }
#pragma unroll
        for (int i = 0; i < 11; ++i) {
            int idx = tid + 256 * i;
            int pp = idx >> 4, qd = idx & 15;
            float4 pv = (qd == g) ? *reinterpret_cast<float4*>(&s.pw[pp * 4]) : z4;
            *reinterpret_cast<float4*>(pmb + (size_t)idx * 4) = pv;
        }
    }

    // ---------- Phase 9: last CTA of batch n normalizes presence ----------
    __syncthreads();
    if (tid == 0) {
        __threadfence();
        int old = atomicAdd(&g_cnt[n], 1);
        s.red[0] = (old == 15) ? 1.f : 0.f;
    }
    __syncthreads();
    if (s.red[0] != 0.f && wid == 0) {
        __threadfence();
        float a = out_pres[n * 64 + lane];
        float b = out_pres[n * 64 + 32 + lane];
        float t = wsum(a + b);
        float inv = 1.0f / fmaxf(t, 1e-6f);
        out_pres[n * 64 + lane] = a * inv;
        out_pres[n * 64 + 32 + lane] = b * inv;
        if (lane == 0) g_cnt[n] = 0;
    }
}

extern "C" void kernel_launch(void* const* d_in, const int* in_sizes, int n_in,
                              void* d_out, int out_size)
{
    const float* x  = (const float*)d_in[0];
    const float* lb = (const float*)d_in[1];
    float* out = (float*)d_out;

    float* tok  = out;
    float* pres = out + TOK_ELEMS;
    float* smap = out + TOK_ELEMS + PRES_ELEMS;
    float* pmap = out + TOK_ELEMS + PRES_ELEMS + MAP_ELEMS;

    fused_stripe_kernel<<<NB * 16, THREADS>>>(x, lb, tok, pres, smap, pmap);
}

// round 6
// speedup vs baseline: 1.3220x; 1.2748x over previous
#include <cuda_runtime.h>
#include <math.h>

#define NB    64
#define CCH   256
#define HW    2816     // 64*44 per channel
#define WW    44
#define PPX   176
#define TOPKK 22
#define TEMP_INV 8.0f
#define GATE_THR 0.05f
#define THREADS 256
#define NUNITS 108     // 22 smap + 64 token + 22 pmap

#define TOK_ELEMS   (NB*CCH*64)
#define PRES_ELEMS  (NB*64)
#define MAP_ELEMS   (NB*64*44*64)

__device__ int g_cnt[NB];   // zero-init; self-resetting each launch

struct __align__(16) SM {
    float lbn4[CCH*4];      // normalized basis packed [c][k]
    float pdP[4*PPX*4];     // dotp partials per channel-subset [cs][p][k]
    float feP[4*PPX];       // fe partials
    float nrmP[4*PPX];      // nrm partials
    float sup[PPX*4];       // support [p][k]
    float pw[PPX*4];        // pool weights [p][k]
    float pwT[4*PPX];       // transposed pool weights [k][p]
    float red[32];
    float scal[16];
    int   ctr;
    int   flag;
};

__device__ __forceinline__ float wsum(float v) {
#pragma unroll
    for (int o = 16; o; o >>= 1) v += __shfl_xor_sync(0xffffffffu, v, o);
    return v;
}
__device__ __forceinline__ float wmaxr(float v) {
#pragma unroll
    for (int o = 16; o; o >>= 1) v = fmaxf(v, __shfl_xor_sync(0xffffffffu, v, o));
    return v;
}

__global__ void __launch_bounds__(THREADS, 4)
fused_stripe_kernel(const float* __restrict__ x, const float* __restrict__ lb,
                    float* __restrict__ out_tok, float* __restrict__ out_pres,
                    float* __restrict__ out_smap, float* __restrict__ out_pmap)
{
    __shared__ SM s;
    const unsigned FULL = 0xffffffffu;
    const int tid = threadIdx.x, lane = tid & 31, wid = tid >> 5;
    const int blk = blockIdx.x;
    const int n = blk >> 4, g = blk & 15;
    const float* xb = x + (size_t)n * (CCH * HW) + (size_t)g * PPX;

    // ---------- Phase 1: load + L2-normalize latent basis ----------
    {
        if (tid == 0) { s.ctr = 0; s.flag = 0; }
        const float* lbg = lb + (size_t)g * (4 * CCH);
        float v0 = lbg[tid], v1 = lbg[CCH + tid], v2 = lbg[2 * CCH + tid], v3 = lbg[3 * CCH + tid];
        float s0 = wsum(v0 * v0), s1 = wsum(v1 * v1), s2 = wsum(v2 * v2), s3 = wsum(v3 * v3);
        if (lane == 0) { s.red[wid] = s0; s.red[8 + wid] = s1; s.red[16 + wid] = s2; s.red[24 + wid] = s3; }
        __syncthreads();
        if (tid < 4) {
            float ss = 0.f;
#pragma unroll
            for (int j = 0; j < 8; ++j) ss += s.red[tid * 8 + j];
            s.scal[tid] = 1.0f / fmaxf(sqrtf(ss), 1e-12f);
        }
        __syncthreads();
        *reinterpret_cast<float4*>(&s.lbn4[tid * 4]) =
            make_float4(v0 * s.scal[0], v1 * s.scal[1], v2 * s.scal[2], v3 * s.scal[3]);
        __syncthreads();
    }

    // ---------- Phase 2: pipelined float4 stencil pass from GMEM ----------
    {
        const int rp = wid >> 2, cs = wid & 3;
        const bool act2 = (lane < 22);
        const int lr = (lane < 22) ? (lane / 11) : 0;
        const int q  = (lane < 22) ? (lane - 11 * lr) : 0;
        const int r  = rp * 2 + lr;
        const int po = act2 ? (r * WW + q * 4) : 0;
        const bool ha = act2 && (r > 0), hc = act2 && (r < 3);
        const float fq0 = (q > 0) ? 1.f : 0.f, fq10 = (q < 10) ? 1.f : 0.f;
        const float4 z4 = make_float4(0.f, 0.f, 0.f, 0.f);

        float4 pd0 = z4, pd1 = z4, pd2 = z4, pd3 = z4, fe4 = z4, nr4 = z4;
        const float4* lbv = reinterpret_cast<const float4*>(s.lbn4);
        const float* pc = xb + po + (size_t)cs * HW;

        // prologue loads
        float4 xm0 = act2 ? *reinterpret_cast<const float4*>(pc) : z4;
        float4 xu0 = ha ? *reinterpret_cast<const float4*>(pc - WW) : z4;
        float4 xd0 = hc ? *reinterpret_cast<const float4*>(pc + WW) : z4;

#pragma unroll 1
        for (int c = cs; c < CCH; c += 4) {
            float4 xm = xm0, xu = xu0, xd = xd0;
            pc += 4 * HW;
            const bool more = (c + 4 < CCH);
            xm0 = (act2 && more) ? *reinterpret_cast<const float4*>(pc) : z4;
            xu0 = (ha && more)   ? *reinterpret_cast<const float4*>(pc - WW) : z4;
            xd0 = (hc && more)   ? *reinterpret_cast<const float4*>(pc + WW) : z4;

            float4 vs = make_float4(xu.x + xm.x + xd.x, xu.y + xm.y + xd.y,
                                    xu.z + xm.z + xd.z, xu.w + xm.w + xd.w);
            float lw = __shfl_up_sync(FULL, vs.w, 1) * fq0;
            float rw = __shfl_down_sync(FULL, vs.x, 1) * fq10;
            float4 pl;
            pl.x = lw + vs.x + vs.y;
            pl.y = vs.x + vs.y + vs.z;
            pl.z = vs.y + vs.z + vs.w;
            pl.w = vs.z + vs.w + rw;
            float4 l4 = lbv[c];
            pd0.x = fmaf(pl.x, l4.x, pd0.x); pd0.y = fmaf(pl.y, l4.x, pd0.y);
            pd0.z = fmaf(pl.z, l4.x, pd0.z); pd0.w = fmaf(pl.w, l4.x, pd0.w);
            pd1.x = fmaf(pl.x, l4.y, pd1.x); pd1.y = fmaf(pl.y, l4.y, pd1.y);
            pd1.z = fmaf(pl.z, l4.y, pd1.z); pd1.w = fmaf(pl.w, l4.y, pd1.w);
            pd2.x = fmaf(pl.x, l4.z, pd2.x); pd2.y = fmaf(pl.y, l4.z, pd2.y);
            pd2.z = fmaf(pl.z, l4.z, pd2.z); pd2.w = fmaf(pl.w, l4.z, pd2.w);
            pd3.x = fmaf(pl.x, l4.w, pd3.x); pd3.y = fmaf(pl.y, l4.w, pd3.y);
            pd3.z = fmaf(pl.z, l4.w, pd3.z); pd3.w = fmaf(pl.w, l4.w, pd3.w);
            fe4.x = fmaf(xm.x, xm.x, fe4.x); fe4.y = fmaf(xm.y, xm.y, fe4.y);
            fe4.z = fmaf(xm.z, xm.z, fe4.z); fe4.w = fmaf(xm.w, xm.w, fe4.w);
            nr4.x = fmaf(pl.x, pl.x, nr4.x); nr4.y = fmaf(pl.y, pl.y, nr4.y);
            nr4.z = fmaf(pl.z, pl.z, nr4.z); nr4.w = fmaf(pl.w, pl.w, nr4.w);
        }
        if (act2) {
            float* pb = &s.pdP[(cs * PPX + po) * 4];
            *reinterpret_cast<float4*>(pb + 0)  = make_float4(pd0.x, pd1.x, pd2.x, pd3.x);
            *reinterpret_cast<float4*>(pb + 4)  = make_float4(pd0.y, pd1.y, pd2.y, pd3.y);
            *reinterpret_cast<float4*>(pb + 8)  = make_float4(pd0.z, pd1.z, pd2.z, pd3.z);
            *reinterpret_cast<float4*>(pb + 12) = make_float4(pd0.w, pd1.w, pd2.w, pd3.w);
            *reinterpret_cast<float4*>(&s.feP[cs * PPX + po])  = fe4;
            *reinterpret_cast<float4*>(&s.nrmP[cs * PPX + po]) = nr4;
        }
    }
    __syncthreads();

    // ---------- Phase 2b: combine partials + fused fe-max ----------
    float dotv0 = 0, dotv1 = 0, dotv2 = 0, dotv3 = 0, fev = 0, nmv = 0;
    if (tid < PPX) {
#pragma unroll
        for (int cs = 0; cs < 4; ++cs) {
            float4 v = *reinterpret_cast<float4*>(&s.pdP[(cs * PPX + tid) * 4]);
            dotv0 += v.x; dotv1 += v.y; dotv2 += v.z; dotv3 += v.w;
            fev += s.feP[cs * PPX + tid];
            nmv += s.nrmP[cs * PPX + tid];
        }
        fev *= (1.0f / CCH);
        nmv *= (1.0f / 81.0f);
    }
    {
        float m = wmaxr((tid < PPX) ? fev : 0.f);
        if (lane == 0) s.red[wid] = m;
    }
    __syncthreads();
    float invmax;
    {
        float mm = s.red[0];
#pragma unroll
        for (int j = 1; j < 8; ++j) mm = fmaxf(mm, s.red[j]);
        invmax = 1.0f / fmaxf(mm, 1e-6f);
    }
    int pred = (tid < PPX) && (fev * invmax > GATE_THR);
    int cnt = __syncthreads_count(pred);

    // ---------- Phase 4: softmax routing -> support ----------
    if (tid < PPX) {
        float rn = 1.0f / fmaxf(sqrtf(nmv), 1e-12f);
        float sc = rn * TEMP_INV * (1.f / 9.f);
        float l0 = dotv0 * sc, l1 = dotv1 * sc, l2 = dotv2 * sc, l3 = dotv3 * sc;
        float m = fmaxf(fmaxf(l0, l1), fmaxf(l2, l3));
        float e0 = __expf(l0 - m), e1 = __expf(l1 - m), e2 = __expf(l2 - m), e3 = __expf(l3 - m);
        float inv = 1.0f / (e0 + e1 + e2 + e3);
        float fes = fev * invmax;
        float act = (cnt > 0) ? (fes > GATE_THR ? 1.f : 0.f) : (fes > 0.f ? 1.f : 0.f);
        float w_ = inv * act;
        *reinterpret_cast<float4*>(&s.sup[tid * 4]) = make_float4(e0 * w_, e1 * w_, e2 * w_, e3 * w_);
    }
    __syncthreads();

    // ---------- Phase 5: overlapped tail ----------
    // warp 0: pool sums -> pw/pwT -> flag.  warps 4-7: top-22 -> join queue.
    // warps 1-3 (and all finished warps): pull work units from smem queue.
    float* smb = out_smap + (size_t)n * (HW * 64) + (size_t)g * (PPX * 64);
    float* pmb = out_pmap + (size_t)n * (HW * 64) + (size_t)g * (PPX * 64);

    if (wid == 0) {
        float s0 = 0, s1 = 0, s2 = 0, s3 = 0;
        for (int pp = lane; pp < PPX; pp += 32) {
            float4 v = *reinterpret_cast<float4*>(&s.sup[pp * 4]);
            s0 += v.x; s1 += v.y; s2 += v.z; s3 += v.w;
        }
        s0 = wsum(s0); s1 = wsum(s1); s2 = wsum(s2); s3 = wsum(s3);
        float i0 = 1.0f / fmaxf(s0, 1e-6f), i1 = 1.0f / fmaxf(s1, 1e-6f);
        float i2 = 1.0f / fmaxf(s2, 1e-6f), i3 = 1.0f / fmaxf(s3, 1e-6f);
        for (int pp = lane; pp < PPX; pp += 32) {
            float4 v = *reinterpret_cast<float4*>(&s.sup[pp * 4]);
            float4 w = make_float4(v.x * i0, v.y * i1, v.z * i2, v.w * i3);
            *reinterpret_cast<float4*>(&s.pw[pp * 4]) = w;
            s.pwT[0 * PPX + pp] = w.x;
            s.pwT[1 * PPX + pp] = w.y;
            s.pwT[2 * PPX + pp] = w.z;
            s.pwT[3 * PPX + pp] = w.w;
        }
        __threadfence_block();
        if (lane == 0) s.flag = 1;
    } else if (wid >= 4) {
        const int k = wid - 4;
        float v[6];
#pragma unroll
        for (int j = 0; j < 6; ++j) {
            int pp = lane + 32 * j;
            v[j] = (pp < PPX) ? s.sup[pp * 4 + k] : -1.0f;
        }
        float sum = 0.f;
        for (int it = 0; it < TOPKK; ++it) {
            float lm = v[0]; int li = 0;
#pragma unroll
            for (int j = 1; j < 6; ++j) { if (v[j] > lm) { lm = v[j]; li = j; } }
            float wm = wmaxr(lm);
            unsigned msk = __ballot_sync(FULL, lm == wm);
            int src = __ffs(msk) - 1;
            if (lane == src) v[li] = -1.0f;
            sum += wm;
        }
        if (lane == 0) {
            out_pres[n * 64 + g * 4 + k] = sum * (1.0f / TOPKK);   // raw
            __threadfence();
        }
    }

    // work queue: units [0,22)=smap, [22,86)=tokens, [86,108)=pmap
    {
        const float4 z4 = make_float4(0.f, 0.f, 0.f, 0.f);
        bool pwReady = false;
        for (;;) {
            int u;
            if (lane == 0) u = atomicAdd(&s.ctr, 1);
            u = __shfl_sync(FULL, u, 0);
            if (u >= NUNITS) break;
            if (u >= 22 && !pwReady) {
                while (*((volatile int*)&s.flag) == 0) {}
                __threadfence_block();
                pwReady = true;
            }
            if (u < 22) {
                // smap unit: 128 float4 slots
                int base = u * 128;
#pragma unroll
                for (int j = 0; j < 4; ++j) {
                    int idx = base + j * 32 + lane;
                    int pp = idx >> 4, qd = idx & 15;
                    float4 sv = (qd == g) ? *reinterpret_cast<float4*>(&s.sup[pp * 4]) : z4;
                    *reinterpret_cast<float4*>(smb + (size_t)idx * 4) = sv;
                }
            } else if (u < 86) {
                // token unit: 4 channels, 8 lanes each
                const int grp = lane >> 3, gl = lane & 7;
                const int c = (u - 22) * 4 + grp;
                const float* xc = xb + (size_t)c * HW;
                float a0 = 0, a1 = 0, a2 = 0, a3 = 0;
#pragma unroll
                for (int it = 0; it < 6; ++it) {
                    int p0 = it * 32 + gl * 4;
                    if (p0 < PPX) {
                        float4 xv = *reinterpret_cast<const float4*>(xc + p0);
                        float4 w0 = *reinterpret_cast<const float4*>(&s.pwT[0 * PPX + p0]);
                        float4 w1 = *reinterpret_cast<const float4*>(&s.pwT[1 * PPX + p0]);
                        float4 w2 = *reinterpret_cast<const float4*>(&s.pwT[2 * PPX + p0]);
                        float4 w3 = *reinterpret_cast<const float4*>(&s.pwT[3 * PPX + p0]);
                        a0 = fmaf(xv.x, w0.x, fmaf(xv.y, w0.y, fmaf(xv.z, w0.z, fmaf(xv.w, w0.w, a0))));
                        a1 = fmaf(xv.x, w1.x, fmaf(xv.y, w1.y, fmaf(xv.z, w1.z, fmaf(xv.w, w1.w, a1))));
                        a2 = fmaf(xv.x, w2.x, fmaf(xv.y, w2.y, fmaf(xv.z, w2.z, fmaf(xv.w, w2.w, a2))));
                        a3 = fmaf(xv.x, w3.x, fmaf(xv.y, w3.y, fmaf(xv.z, w3.z, fmaf(xv.w, w3.w, a3))));
                    }
                }
#pragma unroll
                for (int m = 1; m <= 4; m <<= 1) {
                    a0 += __shfl_xor_sync(FULL, a0, m);
                    a1 += __shfl_xor_sync(FULL, a1, m);
                    a2 += __shfl_xor_sync(FULL, a2, m);
                    a3 += __shfl_xor_sync(FULL, a3, m);
                }
                if (gl == 0)
                    *reinterpret_cast<float4*>(out_tok + ((size_t)(n * CCH + c) * 64 + g * 4)) =
                        make_float4(a0, a1, a2, a3);
            } else {
                // pmap unit: 128 float4 slots
                int base = (u - 86) * 128;
#pragma unroll
                for (int j = 0; j < 4; ++j) {
                    int idx = base + j * 32 + lane;
                    int pp = idx >> 4, qd = idx & 15;
                    float4 pv = (qd == g) ? *reinterpret_cast<float4*>(&s.pw[pp * 4]) : z4;
                    *reinterpret_cast<float4*>(pmb + (size_t)idx * 4) = pv;
                }
            }
        }
    }

    // ---------- Phase 9: last CTA of batch n normalizes presence ----------
    __syncthreads();
    if (tid == 0) {
        __threadfence();
        int old = atomicAdd(&g_cnt[n], 1);
        s.red[0] = (old == 15) ? 1.f : 0.f;
    }
    __syncthreads();
    if (s.red[0] != 0.f && wid == 0) {
        __threadfence();
        float a = out_pres[n * 64 + lane];
        float b = out_pres[n * 64 + 32 + lane];
        float t = wsum(a + b);
        float inv = 1.0f / fmaxf(t, 1e-6f);
        out_pres[n * 64 + lane] = a * inv;
        out_pres[n * 64 + 32 + lane] = b * inv;
        if (lane == 0) g_cnt[n] = 0;
    }
}

extern "C" void kernel_launch(void* const* d_in, const int* in_sizes, int n_in,
                              void* d_out, int out_size)
{
    const float* x  = (const float*)d_in[0];
    const float* lb = (const float*)d_in[1];
    float* out = (float*)d_out;

    float* tok  = out;
    float* pres = out + TOK_ELEMS;
    float* smap = out + TOK_ELEMS + PRES_ELEMS;
    float* pmap = out + TOK_ELEMS + PRES_ELEMS + MAP_ELEMS;

    fused_stripe_kernel<<<NB * 16, THREADS>>>(x, lb, tok, pres, smap, pmap);
}